// round 1
// baseline (speedup 1.0000x reference)
#include <cuda_runtime.h>

#define NB 256        // batch N
#define IN_F 1024
#define B_EXTRA 256
#define KDIM 16
#define OUT_F 1280
#define JDIM (B_EXTRA * KDIM)   // 4096

// Scratch for M = x @ T_flat  (256 x 4096 f32 = 4 MB)
__device__ float g_M[NB * JDIM];

// ---------------------------------------------------------------------------
// Kernel 1: SGEMM  M(256x4096) = x(256x1024) @ W(1024x4096)
// W is T viewed as (1024, 4096) row-major (exactly its memory layout).
// Tiles: BM=64, BN=64, BK=16; 256 threads; 4x4 microtile per thread.
// ---------------------------------------------------------------------------
#define BM 64
#define BN 64
#define BK 16

__global__ __launch_bounds__(256) void gemm_kernel(const float* __restrict__ x,
                                                   const float* __restrict__ W) {
    __shared__ float As[BK][BM + 4];   // transposed A tile, padded (stride 68)
    __shared__ float Bs[BK][BN];

    const int bn = blockIdx.x;   // 0..63  (N tiles)
    const int bm = blockIdx.y;   // 0..3   (M tiles)
    const int tid = threadIdx.x;
    const int tx = tid & 15;     // 0..15 -> 4 cols each
    const int ty = tid >> 4;     // 0..15 -> 4 rows each

    const float* xg = x + bm * BM * IN_F;
    const float* Wg = W + bn * BN;

    float acc[4][4];
#pragma unroll
    for (int i = 0; i < 4; i++)
#pragma unroll
        for (int j = 0; j < 4; j++) acc[i][j] = 0.0f;

    for (int k0 = 0; k0 < IN_F; k0 += BK) {
        // A tile: 64 rows x 16 k -> As[k][row]
        {
            const int c = tid & 15;      // k within tile
            const int r0 = tid >> 4;     // row base
#pragma unroll
            for (int p = 0; p < 4; p++) {
                const int r = r0 + p * 16;
                As[c][r] = xg[r * IN_F + k0 + c];
            }
        }
        // B tile: 16 k x 64 cols -> Bs[k][col]
        {
            const int c = tid & 63;
            const int kr0 = tid >> 6;
#pragma unroll
            for (int p = 0; p < 4; p++) {
                const int kr = kr0 + p * 4;
                Bs[kr][c] = Wg[(k0 + kr) * JDIM + c];
            }
        }
        __syncthreads();

#pragma unroll
        for (int k = 0; k < BK; k++) {
            const float4 a4 = *(const float4*)&As[k][ty * 4];
            const float4 b4 = *(const float4*)&Bs[k][tx * 4];
            const float a[4] = {a4.x, a4.y, a4.z, a4.w};
            const float b[4] = {b4.x, b4.y, b4.z, b4.w};
#pragma unroll
            for (int i = 0; i < 4; i++)
#pragma unroll
                for (int j = 0; j < 4; j++)
                    acc[i][j] = fmaf(a[i], b[j], acc[i][j]);
        }
        __syncthreads();
    }

#pragma unroll
    for (int i = 0; i < 4; i++) {
        const int row = bm * BM + ty * 4 + i;
        float4 v = make_float4(acc[i][0], acc[i][1], acc[i][2], acc[i][3]);
        *(float4*)&g_M[row * JDIM + bn * BN + tx * 4] = v;
    }
}

// ---------------------------------------------------------------------------
// Kernel 2: pairwise L1 + exp-sum.
// Grid = 256 blocks (one per b), 256 threads (one per sample m).
// out[m][1024+b] = sum_n exp(-sum_k |M[n,b,k] - M[m,b,k]|) - 1
// ---------------------------------------------------------------------------
__global__ __launch_bounds__(256) void pairwise_kernel(float* __restrict__ out) {
    __shared__ float sM[NB][KDIM];   // 16 KB: M[:, b, :]

    const int b = blockIdx.x;
    const int tid = threadIdx.x;

    // Load the 256 x 16 column-block for this b (vectorized float4).
    const float4* Mg = (const float4*)g_M;
    float4* sM4 = (float4*)sM;
#pragma unroll
    for (int p = 0; p < 4; p++) {
        const int idx = tid + p * 256;       // 0..1023 float4s
        const int row = idx >> 2;
        const int q = idx & 3;
        sM4[row * 4 + q] = Mg[row * (JDIM / 4) + b * 4 + q];
    }
    __syncthreads();

    float my[KDIM];
#pragma unroll
    for (int k = 0; k < KDIM; k++) my[k] = sM[tid][k];

    float acc = 0.0f;
#pragma unroll 4
    for (int n = 0; n < NB; n++) {
        float l1 = 0.0f;
#pragma unroll
        for (int k = 0; k < KDIM; k++)
            l1 += fabsf(sM[n][k] - my[k]);
        acc += __expf(-l1);
    }

    // self term contributed exp(0)=1; reference subtracts it.
    out[tid * OUT_F + IN_F + b] = acc - 1.0f;
}

// ---------------------------------------------------------------------------
// Kernel 3: copy x into out[:, 0:1024]  (float4 vectorized)
// ---------------------------------------------------------------------------
__global__ __launch_bounds__(256) void copy_x_kernel(const float* __restrict__ x,
                                                     float* __restrict__ out) {
    const int t = blockIdx.x * blockDim.x + threadIdx.x;   // 0..65535 float4s
    const int row = t >> 8;        // 256 float4 per row
    const int c = t & 255;
    const float4 v = ((const float4*)(x + row * IN_F))[c];
    ((float4*)(out + row * OUT_F))[c] = v;
}

extern "C" void kernel_launch(void* const* d_in, const int* in_sizes, int n_in,
                              void* d_out, int out_size) {
    const float* x = (const float*)d_in[0];   // (256, 1024)
    const float* T = (const float*)d_in[1];   // (1024, 256, 16) == W(1024, 4096)
    float* out = (float*)d_out;               // (256, 1280)

    dim3 gemm_grid(JDIM / BN, NB / BM);       // (64, 4)
    gemm_kernel<<<gemm_grid, 256>>>(x, T);

    pairwise_kernel<<<B_EXTRA, NB>>>(out);

    copy_x_kernel<<<(NB * IN_F / 4) / 256, 256>>>(x, out);
}